// round 15
// baseline (speedup 1.0000x reference)
#include <cuda_runtime.h>
#include <cuda_bf16.h>
#include <stdint.h>
#include <math.h>

#define BB 128
#define SS 512
#define DD 1024
#define GEN_V 50000
#define OUT_V 50257

#define NT 96                         // N columns per CTA (521 CTAs)
#define KC 32                         // K per chunk
#define NCHUNK (DD / KC)              // 32
#define NCTA ((GEN_V + NT - 1) / NT)  // 521

// ---------------------------------------------------------------------------
// Device scratch
// ---------------------------------------------------------------------------
__device__ float   g_interp[BB];
__device__ float   g_rowsum[BB];
__device__ uint8_t g_Ahi[NCHUNK * 8192];   // pre-swizzled bf16 A, 8KB per K-chunk

// ---------------------------------------------------------------------------
// Helpers (family-safe PTX only)
// ---------------------------------------------------------------------------
__device__ __forceinline__ uint32_t smem_u32(const void* p) {
    uint32_t a;
    asm("{ .reg .u64 t; cvta.to.shared.u64 t, %1; cvt.u32.u64 %0, t; }" : "=r"(a) : "l"(p));
    return a;
}

#define LDSM4(r, addr)                                                          \
    asm volatile("ldmatrix.sync.aligned.m8n8.x4.shared.b16 {%0,%1,%2,%3}, [%4];" \
        : "=r"((r)[0]), "=r"((r)[1]), "=r"((r)[2]), "=r"((r)[3]) : "r"(addr))

#define LDSM4T(r, addr)                                                               \
    asm volatile("ldmatrix.sync.aligned.m8n8.x4.trans.shared.b16 {%0,%1,%2,%3}, [%4];" \
        : "=r"((r)[0]), "=r"((r)[1]), "=r"((r)[2]), "=r"((r)[3]) : "r"(addr))

#define MMA_BF16(ac, a, b0, b1)                                                  \
    asm volatile("mma.sync.aligned.m16n8k16.row.col.f32.bf16.bf16.f32 "          \
        "{%0,%1,%2,%3}, {%4,%5,%6,%7}, {%8,%9}, {%0,%1,%2,%3};"                  \
        : "+f"((ac)[0]), "+f"((ac)[1]), "+f"((ac)[2]), "+f"((ac)[3])             \
        : "r"((a)[0]), "r"((a)[1]), "r"((a)[2]), "r"((a)[3]), "r"(b0), "r"(b1))

#define CPASYNC16(dst, src) \
    asm volatile("cp.async.ca.shared.global [%0], [%1], 16;" :: "r"(dst), "l"(src))
#define CPASYNC_COMMIT() asm volatile("cp.async.commit_group;")
#define CPASYNC_WAIT1()  asm volatile("cp.async.wait_group 1;" ::: "memory")

__device__ __forceinline__ uint32_t pack_bf16(float lo, float hi) {
    uint32_t r;
    asm("cvt.rn.bf16x2.f32 %0, %1, %2;" : "=r"(r) : "f"(hi), "f"(lo));
    return r;
}

// A chunk swizzle: o = m*64 + k*2, swizzled o ^ (((m>>1)&7)*16)
__device__ __host__ __forceinline__ uint32_t a_swz(int m, int k) {
    uint32_t o = (uint32_t)(m * 64 + k * 2);
    return o ^ ((((uint32_t)m >> 1) & 7u) << 4);
}

// ---------------------------------------------------------------------------
// Fused prep: blocks 0..127 gate, 128..255 prepA, 256.. zero out
// ---------------------------------------------------------------------------
__global__ void prep_kernel(const float* __restrict__ x,
                            const float* __restrict__ Wg,
                            const float* __restrict__ bg,
                            float4* __restrict__ out, int n4) {
    int blk = blockIdx.x;
    int tid = threadIdx.x;
    if (blk < BB) {
        int b = blk;
        if (tid == 0) g_rowsum[b] = 0.f;
        float s = 0.f;
        for (int d = tid; d < DD; d += 256)
            s += x[b * DD + d] * Wg[d];
        __shared__ float red[256];
        red[tid] = s;
        __syncthreads();
        for (int off = 128; off > 0; off >>= 1) {
            if (tid < off) red[tid] += red[tid + off];
            __syncthreads();
        }
        if (tid == 0)
            g_interp[b] = 1.f / (1.f + expf(-(red[0] + bg[0])));
    } else if (blk < 2 * BB) {
        int m = blk - BB;
        for (int k = tid; k < DD; k += 256) {
            float v = x[m * DD + k];
            int c = k >> 5, kk = k & 31;
            *(__nv_bfloat16*)(g_Ahi + (uint32_t)c * 8192u + a_swz(m, kk)) =
                __float2bfloat16(v);
        }
    } else {
        int i = (blk - 2 * BB) * 256 + tid;
        int stride = (gridDim.x - 2 * BB) * 256;
        for (; i < n4; i += stride) out[i] = make_float4(0.f, 0.f, 0.f, 0.f);
    }
}

// ---------------------------------------------------------------------------
// Pure-bf16 GEMM (mma.sync). 256 threads, warp grid 4m x 2n, warp tile 32x48,
// CTA tile 128x96, OCCUPANCY 3 (reg-dieted: split-half B staging, pf = 8 regs).
// Single barrier per chunk. SMEM: bias 512 | g2o 512 | A ring 3x8K | B 2x8K
// ---------------------------------------------------------------------------
#define OFF_G2O  512
#define OFF_A    1024
#define OFF_BBF  25600
#define SMEM_SZ  41984

__global__ __launch_bounds__(256, 3) void gemm_mma_kernel(
    const float* __restrict__ W, const float* __restrict__ bias,
    const int* __restrict__ g2o, float* __restrict__ out)
{
    __shared__ __align__(1024) uint8_t smem[SMEM_SZ];
    const uint32_t sb = smem_u32(smem);

    const int tid = threadIdx.x;
    const int wid = tid >> 5;
    const int lid = tid & 31;
    const int wm = wid >> 1;          // 0..3 (M)
    const int wn = wid & 1;           // 0..1 (N)
    const int n0 = blockIdx.x * NT;

    float* sBias = (float*)(smem);
    int*   sG2O  = (int*)(smem + OFF_G2O);

    if (tid < NT) {
        int gn = n0 + tid;
        bool ok = gn < GEN_V;
        sBias[tid] = ok ? bias[gn] : 0.f;
        sG2O[tid]  = ok ? g2o[gn] : 0;
    }

    // ---- B loader: one k-row (bk0 or bk0+16) x 8 n per half-phase ----
    const int bk0 = tid >> 4;           // 0..15
    const int ng  = (tid & 15) * 8;     // n offset (0..120; active if <96)
    const bool bact = (ng < NT) && (n0 + ng < GEN_V);

    float4 pf[2];   // one k-row's 8 floats

    // load k-row (bk0 + half*16) of chunk c
    auto loadBh = [&](int c, int half) {
        const float* p = W + (size_t)(c * KC + bk0 + half * 16) * GEN_V + n0 + ng;
        if (bact) {
            pf[0] = *(const float4*)(p);
            pf[1] = *(const float4*)(p + 4);
        } else {
            pf[0] = pf[1] = make_float4(0.f, 0.f, 0.f, 0.f);
        }
    };

    auto storeBh = [&](int buf, int half) {
        if (ng >= NT) return;           // cols 96..127 never read
        int k = bk0 + half * 16;
        uint32_t u[4];
        u[0] = pack_bf16(pf[0].x, pf[0].y);
        u[1] = pack_bf16(pf[0].z, pf[0].w);
        u[2] = pack_bf16(pf[1].x, pf[1].y);
        u[3] = pack_bf16(pf[1].z, pf[1].w);
        uint32_t off = (uint32_t)k * 256u +
                       (((uint32_t)ng * 2u) ^ (((uint32_t)k & 7u) << 4));
        *(uint4*)(smem + OFF_BBF + buf * 8192 + off) = *(uint4*)u;
    };

    auto loadA_async = [&](int c) {
        const uint8_t* src = g_Ahi + (size_t)c * 8192 + tid * 32;
        uint32_t dst = sb + OFF_A + (c % 3) * 8192 + tid * 32;
        CPASYNC16(dst, src);
        CPASYNC16(dst + 16, src + 16);
    };

    float acc[2][6][4];
    #pragma unroll
    for (int i = 0; i < 2; i++)
        #pragma unroll
        for (int j = 0; j < 6; j++)
            #pragma unroll
            for (int q = 0; q < 4; q++)
                acc[i][j][q] = 0.f;

    // ldmatrix lane address components
    const int arow = wm * 32 + (lid & 15);
    const int akb  = (lid >> 4) << 4;
    const int bkrow_base = (lid & 15);
    const int bnoff = (lid >> 4) << 3;

    // one MMA ks-half
    auto mma_ks = [&](uint32_t abuf, uint32_t bbuf, int ks) {
        uint32_t ah[2][4];
        #pragma unroll
        for (int i = 0; i < 2; i++) {
            int row = arow + i * 16;
            uint32_t o = (uint32_t)(row * 64 + ks * 32 + akb);
            uint32_t swz = o ^ ((((uint32_t)row >> 1) & 7u) << 4);
            LDSM4(ah[i], abuf + swz);
        }
        #pragma unroll
        for (int j = 0; j < 3; j++) {
            int krow = ks * 16 + bkrow_base;
            int n = wn * 48 + j * 16 + bnoff;
            uint32_t off = (uint32_t)krow * 256u +
                           (((uint32_t)n * 2u) ^ (((uint32_t)krow & 7u) << 4));
            uint32_t bh[4];
            LDSM4T(bh, bbuf + off);
            #pragma unroll
            for (int i = 0; i < 2; i++) {
                MMA_BF16(acc[i][j * 2 + 0], ah[i], bh[0], bh[1]);
                MMA_BF16(acc[i][j * 2 + 1], ah[i], bh[2], bh[3]);
            }
        }
    };

    // ---- Prologue ----
    loadA_async(0); CPASYNC_COMMIT();      // group A0
    loadA_async(1); CPASYNC_COMMIT();      // group A1
    loadBh(0, 0); storeBh(0, 0);
    loadBh(0, 1); storeBh(0, 1);            // buf0 = B(0)
    loadBh(1, 0);                           // pf = half0 of B(1)
    CPASYNC_WAIT1();                        // A0 done, A1 flying
    __syncthreads();

    #pragma unroll 1
    for (int c = 0; c < NCHUNK; c++) {
        const uint32_t abuf = sb + OFF_A + (c % 3) * 8192;
        const uint32_t bbuf = sb + OFF_BBF + (c & 1) * 8192;
        const int nxt = (c + 1) & 1;

        // stage half0 of B(c+1), issue LDG half1
        if (c + 1 < NCHUNK) {
            storeBh(nxt, 0);                // pf from previous iteration
            loadBh(c + 1, 1);
        }

        mma_ks(abuf, bbuf, 0);

        // stage half1 of B(c+1), issue LDG half0 of B(c+2)
        if (c + 1 < NCHUNK) {
            storeBh(nxt, 1);
            if (c + 2 < NCHUNK)
                loadBh(c + 2, 0);           // pf survives barrier to next iter
        }

        mma_ks(abuf, bbuf, 1);

        // A prefetch + wait + single barrier
        if (c + 1 < NCHUNK) {
            if (c + 2 < NCHUNK)
                loadA_async(c + 2);         // -> slot (c+2)%3
            CPASYNC_COMMIT();
            CPASYNC_WAIT1();                // A(c+1) done
            __syncthreads();
        }
    }

    // ---- Epilogue: bias + exp + direct atomic scatter + rowsum ----
    #pragma unroll
    for (int i = 0; i < 2; i++) {
        int r0 = wm * 32 + i * 16 + (lid >> 2);
        int r1 = r0 + 8;
        float s0 = 0.f, s1 = 0.f;
        #pragma unroll
        for (int j = 0; j < 6; j++) {
            int cidx = wn * 48 + j * 8 + (lid & 3) * 2;
            int gn = n0 + cidx;
            if (gn < GEN_V) {
                float b0 = sBias[cidx], b1 = sBias[cidx + 1];
                int o0 = sG2O[cidx], o1 = sG2O[cidx + 1];
                float p00 = __expf(acc[i][j][0] + b0);
                float p01 = __expf(acc[i][j][1] + b1);
                float p10 = __expf(acc[i][j][2] + b0);
                float p11 = __expf(acc[i][j][3] + b1);
                atomicAdd(out + (size_t)r0 * OUT_V + o0, p00);
                atomicAdd(out + (size_t)r0 * OUT_V + o1, p01);
                atomicAdd(out + (size_t)r1 * OUT_V + o0, p10);
                atomicAdd(out + (size_t)r1 * OUT_V + o1, p11);
                s0 += p00 + p01;
                s1 += p10 + p11;
            }
        }
        s0 += __shfl_xor_sync(0xFFFFFFFF, s0, 1);
        s0 += __shfl_xor_sync(0xFFFFFFFF, s0, 2);
        s1 += __shfl_xor_sync(0xFFFFFFFF, s1, 1);
        s1 += __shfl_xor_sync(0xFFFFFFFF, s1, 2);
        if ((lid & 3) == 0) {
            atomicAdd(&g_rowsum[r0], s0);
            atomicAdd(&g_rowsum[r1], s1);
        }
    }
}

// ---------------------------------------------------------------------------
// Rescale: out[b,:] *= interp[b] / rowsum[b]  (flat float4, row per element)
// ---------------------------------------------------------------------------
__global__ void rescale_kernel(float* __restrict__ out) {
    const long n = (long)BB * OUT_V;
    const long n4 = n >> 2;
    float4* o4 = (float4*)out;
    __shared__ float sScale[BB];
    for (int b = threadIdx.x; b < BB; b += 256)
        sScale[b] = g_interp[b] / g_rowsum[b];
    __syncthreads();
    long stride = (long)gridDim.x * 256;
    for (long i = (long)blockIdx.x * 256 + threadIdx.x; i < n4; i += stride) {
        long e = i << 2;
        int b0 = (int)(e / OUT_V);
        int b3 = (int)((e + 3) / OUT_V);
        float4 v = o4[i];
        if (b0 == b3) {
            float s = sScale[b0];
            v.x *= s; v.y *= s; v.z *= s; v.w *= s;
        } else {
            v.x *= sScale[(int)((e + 0) / OUT_V)];
            v.y *= sScale[(int)((e + 1) / OUT_V)];
            v.z *= sScale[(int)((e + 2) / OUT_V)];
            v.w *= sScale[(int)((e + 3) / OUT_V)];
        }
        o4[i] = v;
    }
}

// ---------------------------------------------------------------------------
// Scatter pointer probs (after rescale)
// ---------------------------------------------------------------------------
__global__ void scatter_ptr_kernel(const float* __restrict__ alphas,
                                   const int* __restrict__ ctx,
                                   const int* __restrict__ i2o,
                                   float* __restrict__ out) {
    int b = blockIdx.y;
    int s = blockIdx.x * 256 + threadIdx.x;
    if (s >= SS) return;
    float w = (1.f - g_interp[b]) * alphas[b * SS + s];
    int o = i2o[ctx[b * SS + s]];
    atomicAdd(&out[(size_t)b * OUT_V + o], w);
}

// ---------------------------------------------------------------------------
// Launch. Inputs: x, alphas, W_gate, b_gate, W_gen, b_gen, ctx_inp,
//                 gen_to_out, inp_to_out
// ---------------------------------------------------------------------------
extern "C" void kernel_launch(void* const* d_in, const int* in_sizes, int n_in,
                              void* d_out, int out_size) {
    const float* x      = (const float*)d_in[0];
    const float* alphas = (const float*)d_in[1];
    const float* W_gate = (const float*)d_in[2];
    const float* b_gate = (const float*)d_in[3];
    const float* W_gen  = (const float*)d_in[4];
    const float* b_gen  = (const float*)d_in[5];
    const int* ctx_inp  = (const int*)d_in[6];
    const int* g2o      = (const int*)d_in[7];
    const int* i2o      = (const int*)d_in[8];
    float* out = (float*)d_out;

    prep_kernel<<<2 * BB + 1536, 256>>>(x, W_gate, b_gate,
                                        (float4*)out, (BB * OUT_V) / 4);
    gemm_mma_kernel<<<NCTA, 256>>>(W_gen, b_gen, g2o, out);
    rescale_kernel<<<1024, 256>>>(out);
    dim3 pgrid((SS + 255) / 256, BB);
    scatter_ptr_kernel<<<pgrid, 256>>>(alphas, ctx_inp, i2o, out);
}

// round 16
// speedup vs baseline: 1.1175x; 1.1175x over previous
#include <cuda_runtime.h>
#include <cuda_bf16.h>
#include <stdint.h>
#include <math.h>

#define BB 128
#define SS 512
#define DD 1024
#define GEN_V 50000
#define OUT_V 50257

#define NT 48                         // N columns per CTA
#define KC 32                         // K per chunk
#define NCHUNK (DD / KC)              // 32
#define NCTA ((GEN_V + NT - 1) / NT)  // 1042

// ---------------------------------------------------------------------------
// Device scratch
// ---------------------------------------------------------------------------
__device__ float   g_interp[BB];
__device__ float   g_rowsum[BB];
__device__ uint8_t g_Ahi[NCHUNK * 8192];   // pre-swizzled bf16 A, 8KB per K-chunk

// ---------------------------------------------------------------------------
// Helpers (family-safe PTX only)
// ---------------------------------------------------------------------------
__device__ __forceinline__ uint32_t smem_u32(const void* p) {
    uint32_t a;
    asm("{ .reg .u64 t; cvta.to.shared.u64 t, %1; cvt.u32.u64 %0, t; }" : "=r"(a) : "l"(p));
    return a;
}

#define LDSM4(r, addr)                                                          \
    asm volatile("ldmatrix.sync.aligned.m8n8.x4.shared.b16 {%0,%1,%2,%3}, [%4];" \
        : "=r"((r)[0]), "=r"((r)[1]), "=r"((r)[2]), "=r"((r)[3]) : "r"(addr))

#define LDSM4T(r, addr)                                                               \
    asm volatile("ldmatrix.sync.aligned.m8n8.x4.trans.shared.b16 {%0,%1,%2,%3}, [%4];" \
        : "=r"((r)[0]), "=r"((r)[1]), "=r"((r)[2]), "=r"((r)[3]) : "r"(addr))

#define MMA_BF16(ac, a, b0, b1)                                                  \
    asm volatile("mma.sync.aligned.m16n8k16.row.col.f32.bf16.bf16.f32 "          \
        "{%0,%1,%2,%3}, {%4,%5,%6,%7}, {%8,%9}, {%0,%1,%2,%3};"                  \
        : "+f"((ac)[0]), "+f"((ac)[1]), "+f"((ac)[2]), "+f"((ac)[3])             \
        : "r"((a)[0]), "r"((a)[1]), "r"((a)[2]), "r"((a)[3]), "r"(b0), "r"(b1))

#define CPASYNC16(dst, src) \
    asm volatile("cp.async.ca.shared.global [%0], [%1], 16;" :: "r"(dst), "l"(src))
#define CPASYNC_COMMIT() asm volatile("cp.async.commit_group;")
#define CPASYNC_WAIT1()  asm volatile("cp.async.wait_group 1;" ::: "memory")

__device__ __forceinline__ uint32_t pack_bf16(float lo, float hi) {
    uint32_t r;
    asm("cvt.rn.bf16x2.f32 %0, %1, %2;" : "=r"(r) : "f"(hi), "f"(lo));
    return r;
}

// A chunk swizzle: o = m*64 + k*2, swizzled o ^ (((m>>1)&7)*16)
__device__ __host__ __forceinline__ uint32_t a_swz(int m, int k) {
    uint32_t o = (uint32_t)(m * 64 + k * 2);
    return o ^ ((((uint32_t)m >> 1) & 7u) << 4);
}

// ---------------------------------------------------------------------------
// Fused prep: blocks 0..127 gate, 128..255 prepA, 256.. zero out
// ---------------------------------------------------------------------------
__global__ void prep_kernel(const float* __restrict__ x,
                            const float* __restrict__ Wg,
                            const float* __restrict__ bg,
                            float4* __restrict__ out, int n4) {
    int blk = blockIdx.x;
    int tid = threadIdx.x;
    if (blk < BB) {
        int b = blk;
        if (tid == 0) g_rowsum[b] = 0.f;
        float s = 0.f;
        for (int d = tid; d < DD; d += 256)
            s += x[b * DD + d] * Wg[d];
        __shared__ float red[256];
        red[tid] = s;
        __syncthreads();
        for (int off = 128; off > 0; off >>= 1) {
            if (tid < off) red[tid] += red[tid + off];
            __syncthreads();
        }
        if (tid == 0)
            g_interp[b] = 1.f / (1.f + expf(-(red[0] + bg[0])));
    } else if (blk < 2 * BB) {
        int m = blk - BB;
        for (int k = tid; k < DD; k += 256) {
            float v = x[m * DD + k];
            int c = k >> 5, kk = k & 31;
            *(__nv_bfloat16*)(g_Ahi + (uint32_t)c * 8192u + a_swz(m, kk)) =
                __float2bfloat16(v);
        }
    } else {
        int i = (blk - 2 * BB) * 256 + tid;
        int stride = (gridDim.x - 2 * BB) * 256;
        for (; i < n4; i += stride) out[i] = make_float4(0.f, 0.f, 0.f, 0.f);
    }
}

// ---------------------------------------------------------------------------
// Pure-bf16 GEMM (mma.sync). CTA tile 128(m) x 48(n), 128 threads (4 warps,
// grid 4m x 1n), warp tile 32x48 — per-warp hot loop identical to the proven
// NT=96 kernel. OCCUPANCY 4: 4 warps/SMSP from 4 independent CTAs.
// B smem rows: 128B stride (64 bf16; cols 48..63 unused).
// SMEM: bias 256 | g2o 256 | pad | A ring 3x8K | B 2x4K = 33 KB
// ---------------------------------------------------------------------------
#define OFF_G2O  256
#define OFF_A    1024
#define OFF_BBF  25600
#define SMEM_SZ  33792

__global__ __launch_bounds__(128, 4) void gemm_mma_kernel(
    const float* __restrict__ W, const float* __restrict__ bias,
    const int* __restrict__ g2o, float* __restrict__ out)
{
    __shared__ __align__(1024) uint8_t smem[SMEM_SZ];
    const uint32_t sb = smem_u32(smem);

    const int tid = threadIdx.x;
    const int wid = tid >> 5;         // 0..3 = wm (M direction)
    const int lid = tid & 31;
    const int wm = wid;
    const int n0 = blockIdx.x * NT;

    float* sBias = (float*)(smem);
    int*   sG2O  = (int*)(smem + OFF_G2O);

    if (tid < NT) {
        int gn = n0 + tid;
        bool ok = gn < GEN_V;
        sBias[tid] = ok ? bias[gn] : 0.f;
        sG2O[tid]  = ok ? g2o[gn] : 0;
    }

    // ---- B loader: 192 tasks (32 k-rows x 6 col-groups of 8), 128+64 split --
    const int k0 = tid / 6,  g0 = tid % 6;              // task tid (0..127)
    const int t2 = tid + 128;
    const int k1 = t2 / 6,   g1 = t2 % 6;               // task 128..191 (tid<64)
    const bool has2 = (tid < 64);
    // GEN_V % 8 == 0 -> each 8-col group fully valid or fully invalid
    const bool ok0 = (n0 + g0 * 8 + 8) <= GEN_V;
    const bool ok1 = has2 && ((n0 + g1 * 8 + 8) <= GEN_V);

    float4 pf[4];   // task0: pf[0..1], task1: pf[2..3]

    auto loadB = [&](int c) {
        const float* p0 = W + (size_t)(c * KC + k0) * GEN_V + n0 + g0 * 8;
        const float* p1 = W + (size_t)(c * KC + k1) * GEN_V + n0 + g1 * 8;
        if (ok0) { pf[0] = *(const float4*)(p0); pf[1] = *(const float4*)(p0 + 4); }
        else     { pf[0] = pf[1] = make_float4(0.f, 0.f, 0.f, 0.f); }
        if (ok1) { pf[2] = *(const float4*)(p1); pf[3] = *(const float4*)(p1 + 4); }
        else     { pf[2] = pf[3] = make_float4(0.f, 0.f, 0.f, 0.f); }
    };

    auto storeB = [&](int buf) {
        {
            uint32_t u[4];
            u[0] = pack_bf16(pf[0].x, pf[0].y);
            u[1] = pack_bf16(pf[0].z, pf[0].w);
            u[2] = pack_bf16(pf[1].x, pf[1].y);
            u[3] = pack_bf16(pf[1].z, pf[1].w);
            uint32_t off = (uint32_t)k0 * 128u +
                           (((uint32_t)(g0 * 16)) ^ (((uint32_t)k0 & 7u) << 4));
            *(uint4*)(smem + OFF_BBF + buf * 4096 + off) = *(uint4*)u;
        }
        if (has2) {
            uint32_t u[4];
            u[0] = pack_bf16(pf[2].x, pf[2].y);
            u[1] = pack_bf16(pf[2].z, pf[2].w);
            u[2] = pack_bf16(pf[3].x, pf[3].y);
            u[3] = pack_bf16(pf[3].z, pf[3].w);
            uint32_t off = (uint32_t)k1 * 128u +
                           (((uint32_t)(g1 * 16)) ^ (((uint32_t)k1 & 7u) << 4));
            *(uint4*)(smem + OFF_BBF + buf * 4096 + off) = *(uint4*)u;
        }
    };

    auto loadA_async = [&](int c) {
        const uint8_t* src = g_Ahi + (size_t)c * 8192 + tid * 64;
        uint32_t dst = sb + OFF_A + (c % 3) * 8192 + tid * 64;
        CPASYNC16(dst, src);
        CPASYNC16(dst + 16, src + 16);
        CPASYNC16(dst + 32, src + 32);
        CPASYNC16(dst + 48, src + 48);
    };

    float acc[2][6][4];
    #pragma unroll
    for (int i = 0; i < 2; i++)
        #pragma unroll
        for (int j = 0; j < 6; j++)
            #pragma unroll
            for (int q = 0; q < 4; q++)
                acc[i][j][q] = 0.f;

    // ldmatrix lane address components
    const int arow = wm * 32 + (lid & 15);
    const int akb  = (lid >> 4) << 4;
    const int bkrow_base = (lid & 15);
    const int bnoff = (lid >> 4) << 3;

    // ---- Prologue ----
    loadA_async(0); CPASYNC_COMMIT();      // group A0
    loadA_async(1); CPASYNC_COMMIT();      // group A1
    loadB(0);
    storeB(0);                              // buf0 = B(0)
    loadB(1);                               // pf = B(1)
    CPASYNC_WAIT1();                        // A0 done, A1 flying
    __syncthreads();

    #pragma unroll 1
    for (int c = 0; c < NCHUNK; c++) {
        // ---- Hoisted staging ----
        if (c + 1 < NCHUNK) {
            storeB((c + 1) & 1);            // consumes pf (chunk c+1)
            if (c + 2 < NCHUNK)
                loadB(c + 2);               // LDG -> pf, covered by MMA(c)
        }

        // ---- MMA over chunk c ----
        const uint32_t abuf = sb + OFF_A + (c % 3) * 8192;
        const uint32_t bbuf = sb + OFF_BBF + (c & 1) * 4096;
        #pragma unroll
        for (int ks = 0; ks < 2; ks++) {
            uint32_t ah[2][4];
            #pragma unroll
            for (int i = 0; i < 2; i++) {
                int row = arow + i * 16;
                uint32_t o = (uint32_t)(row * 64 + ks * 32 + akb);
                uint32_t swz = o ^ ((((uint32_t)row >> 1) & 7u) << 4);
                LDSM4(ah[i], abuf + swz);
            }
            #pragma unroll
            for (int j = 0; j < 3; j++) {
                int krow = ks * 16 + bkrow_base;
                int n = j * 16 + bnoff;
                uint32_t off = (uint32_t)krow * 128u +
                               (((uint32_t)(n * 2)) ^ (((uint32_t)krow & 7u) << 4));
                uint32_t bh[4];
                LDSM4T(bh, bbuf + off);
                #pragma unroll
                for (int i = 0; i < 2; i++) {
                    MMA_BF16(acc[i][j * 2 + 0], ah[i], bh[0], bh[1]);
                    MMA_BF16(acc[i][j * 2 + 1], ah[i], bh[2], bh[3]);
                }
            }
        }

        // ---- Post-MMA: A prefetch + wait + single barrier ----
        if (c + 1 < NCHUNK) {
            if (c + 2 < NCHUNK)
                loadA_async(c + 2);         // -> slot (c+2)%3
            CPASYNC_COMMIT();
            CPASYNC_WAIT1();                // A(c+1) done
            __syncthreads();
        }
    }

    // ---- Epilogue: bias + exp + direct atomic scatter + rowsum ----
    #pragma unroll
    for (int i = 0; i < 2; i++) {
        int r0 = wm * 32 + i * 16 + (lid >> 2);
        int r1 = r0 + 8;
        float s0 = 0.f, s1 = 0.f;
        #pragma unroll
        for (int j = 0; j < 6; j++) {
            int cidx = j * 8 + (lid & 3) * 2;
            int gn = n0 + cidx;
            if (gn < GEN_V) {
                float b0 = sBias[cidx], b1 = sBias[cidx + 1];
                int o0 = sG2O[cidx], o1 = sG2O[cidx + 1];
                float p00 = __expf(acc[i][j][0] + b0);
                float p01 = __expf(acc[i][j][1] + b1);
                float p10 = __expf(acc[i][j][2] + b0);
                float p11 = __expf(acc[i][j][3] + b1);
                atomicAdd(out + (size_t)r0 * OUT_V + o0, p00);
                atomicAdd(out + (size_t)r0 * OUT_V + o1, p01);
                atomicAdd(out + (size_t)r1 * OUT_V + o0, p10);
                atomicAdd(out + (size_t)r1 * OUT_V + o1, p11);
                s0 += p00 + p01;
                s1 += p10 + p11;
            }
        }
        s0 += __shfl_xor_sync(0xFFFFFFFF, s0, 1);
        s0 += __shfl_xor_sync(0xFFFFFFFF, s0, 2);
        s1 += __shfl_xor_sync(0xFFFFFFFF, s1, 1);
        s1 += __shfl_xor_sync(0xFFFFFFFF, s1, 2);
        if ((lid & 3) == 0) {
            atomicAdd(&g_rowsum[r0], s0);
            atomicAdd(&g_rowsum[r1], s1);
        }
    }
}

// ---------------------------------------------------------------------------
// Rescale: out[b,:] *= interp[b] / rowsum[b]  (flat float4, row per element)
// ---------------------------------------------------------------------------
__global__ void rescale_kernel(float* __restrict__ out) {
    const long n = (long)BB * OUT_V;
    const long n4 = n >> 2;
    float4* o4 = (float4*)out;
    __shared__ float sScale[BB];
    for (int b = threadIdx.x; b < BB; b += 256)
        sScale[b] = g_interp[b] / g_rowsum[b];
    __syncthreads();
    long stride = (long)gridDim.x * 256;
    for (long i = (long)blockIdx.x * 256 + threadIdx.x; i < n4; i += stride) {
        long e = i << 2;
        int b0 = (int)(e / OUT_V);
        int b3 = (int)((e + 3) / OUT_V);
        float4 v = o4[i];
        if (b0 == b3) {
            float s = sScale[b0];
            v.x *= s; v.y *= s; v.z *= s; v.w *= s;
        } else {
            v.x *= sScale[(int)((e + 0) / OUT_V)];
            v.y *= sScale[(int)((e + 1) / OUT_V)];
            v.z *= sScale[(int)((e + 2) / OUT_V)];
            v.w *= sScale[(int)((e + 3) / OUT_V)];
        }
        o4[i] = v;
    }
}

// ---------------------------------------------------------------------------
// Scatter pointer probs (after rescale)
// ---------------------------------------------------------------------------
__global__ void scatter_ptr_kernel(const float* __restrict__ alphas,
                                   const int* __restrict__ ctx,
                                   const int* __restrict__ i2o,
                                   float* __restrict__ out) {
    int b = blockIdx.y;
    int s = blockIdx.x * 256 + threadIdx.x;
    if (s >= SS) return;
    float w = (1.f - g_interp[b]) * alphas[b * SS + s];
    int o = i2o[ctx[b * SS + s]];
    atomicAdd(&out[(size_t)b * OUT_V + o], w);
}

// ---------------------------------------------------------------------------
// Launch. Inputs: x, alphas, W_gate, b_gate, W_gen, b_gen, ctx_inp,
//                 gen_to_out, inp_to_out
// ---------------------------------------------------------------------------
extern "C" void kernel_launch(void* const* d_in, const int* in_sizes, int n_in,
                              void* d_out, int out_size) {
    const float* x      = (const float*)d_in[0];
    const float* alphas = (const float*)d_in[1];
    const float* W_gate = (const float*)d_in[2];
    const float* b_gate = (const float*)d_in[3];
    const float* W_gen  = (const float*)d_in[4];
    const float* b_gen  = (const float*)d_in[5];
    const int* ctx_inp  = (const int*)d_in[6];
    const int* g2o      = (const int*)d_in[7];
    const int* i2o      = (const int*)d_in[8];
    float* out = (float*)d_out;

    prep_kernel<<<2 * BB + 1536, 256>>>(x, W_gate, b_gate,
                                        (float4*)out, (BB * OUT_V) / 4);
    gemm_mma_kernel<<<NCTA, 128>>>(W_gen, b_gen, g2o, out);
    rescale_kernel<<<1024, 256>>>(out);
    dim3 pgrid((SS + 255) / 256, BB);
    scatter_ptr_kernel<<<pgrid, 256>>>(alphas, ctx_inp, i2o, out);
}

// round 17
// speedup vs baseline: 1.3162x; 1.1778x over previous
#include <cuda_runtime.h>
#include <cuda_bf16.h>
#include <stdint.h>
#include <math.h>

#define BB 128
#define SS 512
#define DD 1024
#define GEN_V 50000
#define OUT_V 50257

#define KC 32
#define NCHUNK (DD / KC)              // 32

// Hybrid split: wave 1 = 296 CTAs x 128 cols = 37888; wave 2 = 190 CTAs x 64
#define SPLIT_COL 37888
#define NCTA1 296
#define NCTA2 190

// ---------------------------------------------------------------------------
// Device scratch
// ---------------------------------------------------------------------------
__device__ float   g_interp[BB];
__device__ float   g_rowsum[BB];
__device__ uint8_t g_Ahi[NCHUNK * 8192];   // pre-swizzled bf16 A, 8KB per K-chunk

// ---------------------------------------------------------------------------
// Helpers (family-safe PTX only)
// ---------------------------------------------------------------------------
__device__ __forceinline__ uint32_t smem_u32(const void* p) {
    uint32_t a;
    asm("{ .reg .u64 t; cvta.to.shared.u64 t, %1; cvt.u32.u64 %0, t; }" : "=r"(a) : "l"(p));
    return a;
}

#define LDSM4(r, addr)                                                          \
    asm volatile("ldmatrix.sync.aligned.m8n8.x4.shared.b16 {%0,%1,%2,%3}, [%4];" \
        : "=r"((r)[0]), "=r"((r)[1]), "=r"((r)[2]), "=r"((r)[3]) : "r"(addr))

#define LDSM4T(r, addr)                                                               \
    asm volatile("ldmatrix.sync.aligned.m8n8.x4.trans.shared.b16 {%0,%1,%2,%3}, [%4];" \
        : "=r"((r)[0]), "=r"((r)[1]), "=r"((r)[2]), "=r"((r)[3]) : "r"(addr))

#define MMA_BF16(ac, a, b0, b1)                                                  \
    asm volatile("mma.sync.aligned.m16n8k16.row.col.f32.bf16.bf16.f32 "          \
        "{%0,%1,%2,%3}, {%4,%5,%6,%7}, {%8,%9}, {%0,%1,%2,%3};"                  \
        : "+f"((ac)[0]), "+f"((ac)[1]), "+f"((ac)[2]), "+f"((ac)[3])             \
        : "r"((a)[0]), "r"((a)[1]), "r"((a)[2]), "r"((a)[3]), "r"(b0), "r"(b1))

#define CPASYNC16(dst, src) \
    asm volatile("cp.async.ca.shared.global [%0], [%1], 16;" :: "r"(dst), "l"(src))
#define CPASYNC_COMMIT() asm volatile("cp.async.commit_group;")
#define CPASYNC_WAIT1()  asm volatile("cp.async.wait_group 1;" ::: "memory")

__device__ __forceinline__ uint32_t pack_bf16(float lo, float hi) {
    uint32_t r;
    asm("cvt.rn.bf16x2.f32 %0, %1, %2;" : "=r"(r) : "f"(hi), "f"(lo));
    return r;
}

// A chunk swizzle: o = m*64 + k*2, swizzled o ^ (((m>>1)&7)*16)
__device__ __host__ __forceinline__ uint32_t a_swz(int m, int k) {
    uint32_t o = (uint32_t)(m * 64 + k * 2);
    return o ^ ((((uint32_t)m >> 1) & 7u) << 4);
}

// ---------------------------------------------------------------------------
// Fused prep: blocks 0..127 gate, 128..255 prepA, 256.. zero out
// ---------------------------------------------------------------------------
__global__ void prep_kernel(const float* __restrict__ x,
                            const float* __restrict__ Wg,
                            const float* __restrict__ bg,
                            float4* __restrict__ out, int n4) {
    int blk = blockIdx.x;
    int tid = threadIdx.x;
    if (blk < BB) {
        int b = blk;
        if (tid == 0) g_rowsum[b] = 0.f;
        float s = 0.f;
        for (int d = tid; d < DD; d += 256)
            s += x[b * DD + d] * Wg[d];
        __shared__ float red[256];
        red[tid] = s;
        __syncthreads();
        for (int off = 128; off > 0; off >>= 1) {
            if (tid < off) red[tid] += red[tid + off];
            __syncthreads();
        }
        if (tid == 0)
            g_interp[b] = 1.f / (1.f + expf(-(red[0] + bg[0])));
    } else if (blk < 2 * BB) {
        int m = blk - BB;
        for (int k = tid; k < DD; k += 256) {
            float v = x[m * DD + k];
            int c = k >> 5, kk = k & 31;
            *(__nv_bfloat16*)(g_Ahi + (uint32_t)c * 8192u + a_swz(m, kk)) =
                __float2bfloat16(v);
        }
    } else {
        int i = (blk - 2 * BB) * 256 + tid;
        int stride = (gridDim.x - 2 * BB) * 256;
        for (; i < n4; i += stride) out[i] = make_float4(0.f, 0.f, 0.f, 0.f);
    }
}

// ---------------------------------------------------------------------------
// Pure-bf16 GEMM (mma.sync), templated on CTA N-tile (NTT = 128 or 64).
// 256 threads, warp grid 4m x 2n, warp tile 32 x (NTT/2). Single-barrier
// pipelined chunks, hoisted staging, fused exp + atomic scatter epilogue.
// B smem rows: 256B stride regardless of NTT (proven swizzle math).
// SMEM: bias 512 | g2o 512 | A ring 3x8K | B 2x8K
// ---------------------------------------------------------------------------
#define OFF_G2O  512
#define OFF_A    1024
#define OFF_BBF  25600
#define SMEM_SZ  41984

template <int NTT>
__global__ __launch_bounds__(256, 2) void gemm_mma_kernel(
    const float* __restrict__ W, const float* __restrict__ bias,
    const int* __restrict__ g2o, float* __restrict__ out, int nbase)
{
    constexpr int G  = NTT / 8;       // col-groups of 8 per k-row (16 or 8)
    constexpr int TT = (32 * G) / 256; // B tasks per thread (2 or 1)
    constexpr int JM = NTT / 32;      // j bound per ks in MMA (4 or 2)
    constexpr int JE = NTT / 16;      // j bound in epilogue (8 or 4)
    constexpr int WN = NTT / 2;       // warp n width (64 or 32)

    __shared__ __align__(1024) uint8_t smem[SMEM_SZ];
    const uint32_t sb = smem_u32(smem);

    const int tid = threadIdx.x;
    const int wid = tid >> 5;
    const int lid = tid & 31;
    const int wm = wid >> 1;          // 0..3 (M)
    const int wn = wid & 1;           // 0..1 (N)
    const int n0 = nbase + blockIdx.x * NTT;

    float* sBias = (float*)(smem);
    int*   sG2O  = (int*)(smem + OFF_G2O);

    if (tid < NTT) {
        int gn = n0 + tid;
        bool ok = gn < GEN_V;
        sBias[tid] = ok ? bias[gn] : 0.f;
        sG2O[tid]  = ok ? g2o[gn] : 0;
    }

    // ---- B loader: TT tasks of (k-row, 8-col group) per thread ----
    int bkv[TT], ngv[TT];
    bool okv[TT];
    #pragma unroll
    for (int t = 0; t < TT; t++) {
        int task = tid + t * 256;
        bkv[t] = task / G;
        ngv[t] = (task % G) * 8;
        okv[t] = (n0 + ngv[t] + 8) <= GEN_V;   // GEN_V%8==0 -> group all-or-none
    }

    float4 pf[2 * TT];

    auto loadB = [&](int c) {
        #pragma unroll
        for (int t = 0; t < TT; t++) {
            const float* p = W + (size_t)(c * KC + bkv[t]) * GEN_V + n0 + ngv[t];
            if (okv[t]) {
                pf[2 * t]     = *(const float4*)(p);
                pf[2 * t + 1] = *(const float4*)(p + 4);
            } else {
                pf[2 * t] = pf[2 * t + 1] = make_float4(0.f, 0.f, 0.f, 0.f);
            }
        }
    };

    auto storeB = [&](int buf) {
        #pragma unroll
        for (int t = 0; t < TT; t++) {
            int k = bkv[t], ng = ngv[t];
            float4 a = pf[2 * t], b4 = pf[2 * t + 1];
            uint32_t u[4];
            u[0] = pack_bf16(a.x, a.y);
            u[1] = pack_bf16(a.z, a.w);
            u[2] = pack_bf16(b4.x, b4.y);
            u[3] = pack_bf16(b4.z, b4.w);
            uint32_t off = (uint32_t)k * 256u +
                           (((uint32_t)ng * 2u) ^ (((uint32_t)k & 7u) << 4));
            *(uint4*)(smem + OFF_BBF + buf * 8192 + off) = *(uint4*)u;
        }
    };

    auto loadA_async = [&](int c) {
        const uint8_t* src = g_Ahi + (size_t)c * 8192 + tid * 32;
        uint32_t dst = sb + OFF_A + (c % 3) * 8192 + tid * 32;
        CPASYNC16(dst, src);
        CPASYNC16(dst + 16, src + 16);
    };

    float acc[2][JE][4];
    #pragma unroll
    for (int i = 0; i < 2; i++)
        #pragma unroll
        for (int j = 0; j < JE; j++)
            #pragma unroll
            for (int q = 0; q < 4; q++)
                acc[i][j][q] = 0.f;

    // ldmatrix lane address components
    const int arow = wm * 32 + (lid & 15);
    const int akb  = (lid >> 4) << 4;
    const int bkrow_base = (lid & 15);
    const int bnoff = (lid >> 4) << 3;

    // ---- Prologue ----
    loadA_async(0); CPASYNC_COMMIT();      // group A0
    loadA_async(1); CPASYNC_COMMIT();      // group A1
    loadB(0);
    storeB(0);                              // buf0 = B(0)
    loadB(1);                               // pf = B(1)
    CPASYNC_WAIT1();                        // A0 done, A1 flying
    __syncthreads();

    #pragma unroll 1
    for (int c = 0; c < NCHUNK; c++) {
        // ---- Hoisted staging ----
        if (c + 1 < NCHUNK) {
            storeB((c + 1) & 1);            // consumes pf (chunk c+1)
            if (c + 2 < NCHUNK)
                loadB(c + 2);               // LDG -> pf, covered by MMA(c)
        }

        // ---- MMA over chunk c ----
        const uint32_t abuf = sb + OFF_A + (c % 3) * 8192;
        const uint32_t bbuf = sb + OFF_BBF + (c & 1) * 8192;
        #pragma unroll
        for (int ks = 0; ks < 2; ks++) {
            uint32_t ah[2][4];
            #pragma unroll
            for (int i = 0; i < 2; i++) {
                int row = arow + i * 16;
                uint32_t o = (uint32_t)(row * 64 + ks * 32 + akb);
                uint32_t swz = o ^ ((((uint32_t)row >> 1) & 7u) << 4);
                LDSM4(ah[i], abuf + swz);
            }
            #pragma unroll
            for (int j = 0; j < JM; j++) {
                int krow = ks * 16 + bkrow_base;
                int n = wn * WN + j * 16 + bnoff;
                uint32_t off = (uint32_t)krow * 256u +
                               (((uint32_t)n * 2u) ^ (((uint32_t)krow & 7u) << 4));
                uint32_t bh[4];
                LDSM4T(bh, bbuf + off);
                #pragma unroll
                for (int i = 0; i < 2; i++) {
                    MMA_BF16(acc[i][j * 2 + 0], ah[i], bh[0], bh[1]);
                    MMA_BF16(acc[i][j * 2 + 1], ah[i], bh[2], bh[3]);
                }
            }
        }

        // ---- Post-MMA: A prefetch + wait + single barrier ----
        if (c + 1 < NCHUNK) {
            if (c + 2 < NCHUNK)
                loadA_async(c + 2);         // -> slot (c+2)%3
            CPASYNC_COMMIT();
            CPASYNC_WAIT1();                // A(c+1) done
            __syncthreads();
        }
    }

    // ---- Epilogue: bias + exp + direct atomic scatter + rowsum ----
    #pragma unroll
    for (int i = 0; i < 2; i++) {
        int r0 = wm * 32 + i * 16 + (lid >> 2);
        int r1 = r0 + 8;
        float s0 = 0.f, s1 = 0.f;
        #pragma unroll
        for (int j = 0; j < JE; j++) {
            int cidx = wn * WN + j * 8 + (lid & 3) * 2;
            int gn = n0 + cidx;
            if (gn < GEN_V) {
                float b0 = sBias[cidx], b1 = sBias[cidx + 1];
                int o0 = sG2O[cidx], o1 = sG2O[cidx + 1];
                float p00 = __expf(acc[i][j][0] + b0);
                float p01 = __expf(acc[i][j][1] + b1);
                float p10 = __expf(acc[i][j][2] + b0);
                float p11 = __expf(acc[i][j][3] + b1);
                atomicAdd(out + (size_t)r0 * OUT_V + o0, p00);
                atomicAdd(out + (size_t)r0 * OUT_V + o1, p01);
                atomicAdd(out + (size_t)r1 * OUT_V + o0, p10);
                atomicAdd(out + (size_t)r1 * OUT_V + o1, p11);
                s0 += p00 + p01;
                s1 += p10 + p11;
            }
        }
        s0 += __shfl_xor_sync(0xFFFFFFFF, s0, 1);
        s0 += __shfl_xor_sync(0xFFFFFFFF, s0, 2);
        s1 += __shfl_xor_sync(0xFFFFFFFF, s1, 1);
        s1 += __shfl_xor_sync(0xFFFFFFFF, s1, 2);
        if ((lid & 3) == 0) {
            atomicAdd(&g_rowsum[r0], s0);
            atomicAdd(&g_rowsum[r1], s1);
        }
    }
}

// ---------------------------------------------------------------------------
// Rescale: out[b,:] *= interp[b] / rowsum[b]  (flat float4, row per element)
// ---------------------------------------------------------------------------
__global__ void rescale_kernel(float* __restrict__ out) {
    const long n = (long)BB * OUT_V;
    const long n4 = n >> 2;
    float4* o4 = (float4*)out;
    __shared__ float sScale[BB];
    for (int b = threadIdx.x; b < BB; b += 256)
        sScale[b] = g_interp[b] / g_rowsum[b];
    __syncthreads();
    long stride = (long)gridDim.x * 256;
    for (long i = (long)blockIdx.x * 256 + threadIdx.x; i < n4; i += stride) {
        long e = i << 2;
        int b0 = (int)(e / OUT_V);
        int b3 = (int)((e + 3) / OUT_V);
        float4 v = o4[i];
        if (b0 == b3) {
            float s = sScale[b0];
            v.x *= s; v.y *= s; v.z *= s; v.w *= s;
        } else {
            v.x *= sScale[(int)((e + 0) / OUT_V)];
            v.y *= sScale[(int)((e + 1) / OUT_V)];
            v.z *= sScale[(int)((e + 2) / OUT_V)];
            v.w *= sScale[(int)((e + 3) / OUT_V)];
        }
        o4[i] = v;
    }
}

// ---------------------------------------------------------------------------
// Scatter pointer probs (after rescale)
// ---------------------------------------------------------------------------
__global__ void scatter_ptr_kernel(const float* __restrict__ alphas,
                                   const int* __restrict__ ctx,
                                   const int* __restrict__ i2o,
                                   float* __restrict__ out) {
    int b = blockIdx.y;
    int s = blockIdx.x * 256 + threadIdx.x;
    if (s >= SS) return;
    float w = (1.f - g_interp[b]) * alphas[b * SS + s];
    int o = i2o[ctx[b * SS + s]];
    atomicAdd(&out[(size_t)b * OUT_V + o], w);
}

// ---------------------------------------------------------------------------
// Launch. Inputs: x, alphas, W_gate, b_gate, W_gen, b_gen, ctx_inp,
//                 gen_to_out, inp_to_out
// ---------------------------------------------------------------------------
extern "C" void kernel_launch(void* const* d_in, const int* in_sizes, int n_in,
                              void* d_out, int out_size) {
    const float* x      = (const float*)d_in[0];
    const float* alphas = (const float*)d_in[1];
    const float* W_gate = (const float*)d_in[2];
    const float* b_gate = (const float*)d_in[3];
    const float* W_gen  = (const float*)d_in[4];
    const float* b_gen  = (const float*)d_in[5];
    const int* ctx_inp  = (const int*)d_in[6];
    const int* g2o      = (const int*)d_in[7];
    const int* i2o      = (const int*)d_in[8];
    float* out = (float*)d_out;

    prep_kernel<<<2 * BB + 1536, 256>>>(x, W_gate, b_gate,
                                        (float4*)out, (BB * OUT_V) / 4);
    // Wave 1: exactly one full wave of NT=128 CTAs
    gemm_mma_kernel<128><<<NCTA1, 256>>>(W_gen, b_gen, g2o, out, 0);
    // Wave 2: remaining 12112 cols in one sub-wave of NT=64 CTAs
    gemm_mma_kernel<64><<<NCTA2, 256>>>(W_gen, b_gen, g2o, out, SPLIT_COL);
    rescale_kernel<<<1024, 256>>>(out);
    dim3 pgrid((SS + 255) / 256, BB);
    scatter_ptr_kernel<<<pgrid, 256>>>(alphas, ctx_inp, i2o, out);
}